// round 2
// baseline (speedup 1.0000x reference)
#include <cuda_runtime.h>
#include <cuda_fp16.h>
#include <cstdint>

// ===================== problem constants =====================
#define M_TOTAL 8192
#define N_TOTAL 4096
#define K_TOTAL 4096
#define THRESH  0.1f

// ===================== GEMM tiling =====================
#define BM 128
#define BN 128
#define BK 64            // halves per k-stage (128 bytes per row)
#define STAGES 3
#define GTHREADS 256     // 8 warps: 2 (M) x 4 (N), each warp 64x32

#define STAGE_HALVES (BM * BK + BN * BK)            // 16384 halves
#define STAGE_BYTES  (STAGE_HALVES * 2)             // 32768
#define SMEM_BYTES   (STAGES * STAGE_BYTES)         // 98304

// ===================== scratch (device globals, allocation-free) ==========
__device__ __half g_A[(size_t)M_TOTAL * K_TOTAL];   // 64 MB, x in fp16
__device__ __half g_B[(size_t)N_TOTAL * K_TOTAL];   // 32 MB, ternary(w) in fp16

// ===================== helpers =====================
static __device__ __forceinline__ uint32_t smem_u32(const void* p) {
    uint32_t a;
    asm("{ .reg .u64 t; cvta.to.shared.u64 t, %1; cvt.u32.u64 %0, t; }"
        : "=r"(a) : "l"(p));
    return a;
}

static __device__ __forceinline__ void cp16(uint32_t dst, const void* src) {
    asm volatile("cp.async.cg.shared.global [%0], [%1], 16;"
                 :: "r"(dst), "l"(src) : "memory");
}
#define CP_COMMIT() asm volatile("cp.async.commit_group;" ::: "memory")
#define CP_WAIT1()  asm volatile("cp.async.wait_group 1;"  ::: "memory")

static __device__ __forceinline__ void ldm_x4(uint32_t* r, uint32_t addr) {
    asm volatile("ldmatrix.sync.aligned.m8n8.x4.shared.b16 {%0,%1,%2,%3}, [%4];"
                 : "=r"(r[0]), "=r"(r[1]), "=r"(r[2]), "=r"(r[3]) : "r"(addr));
}

static __device__ __forceinline__ void mma16816(float* c, const uint32_t* a,
                                                uint32_t b0, uint32_t b1) {
    asm volatile(
        "mma.sync.aligned.m16n8k16.row.col.f32.f16.f16.f32 "
        "{%0,%1,%2,%3}, {%4,%5,%6,%7}, {%8,%9}, {%0,%1,%2,%3};"
        : "+f"(c[0]), "+f"(c[1]), "+f"(c[2]), "+f"(c[3])
        : "r"(a[0]), "r"(a[1]), "r"(a[2]), "r"(a[3]), "r"(b0), "r"(b1));
}

// ===================== pack kernels =====================
__global__ void __launch_bounds__(256) pack_x_kernel(const float4* __restrict__ x) {
    size_t i = (size_t)blockIdx.x * blockDim.x + threadIdx.x;
    const size_t total = (size_t)M_TOTAL * K_TOTAL / 4;
    if (i >= total) return;
    float4 v = x[i];
    __half2 h0 = __floats2half2_rn(v.x, v.y);
    __half2 h1 = __floats2half2_rn(v.z, v.w);
    uint32_t u0 = *(uint32_t*)&h0, u1 = *(uint32_t*)&h1;
    *(uint2*)(&g_A[i * 4]) = make_uint2(u0, u1);
}

__global__ void __launch_bounds__(256) pack_w_kernel(const float4* __restrict__ w) {
    size_t i = (size_t)blockIdx.x * blockDim.x + threadIdx.x;
    const size_t total = (size_t)N_TOTAL * K_TOTAL / 4;
    if (i >= total) return;
    float4 v = w[i];
    float q0 = (v.x > THRESH) ? 1.0f : ((v.x < -THRESH) ? -1.0f : 0.0f);
    float q1 = (v.y > THRESH) ? 1.0f : ((v.y < -THRESH) ? -1.0f : 0.0f);
    float q2 = (v.z > THRESH) ? 1.0f : ((v.z < -THRESH) ? -1.0f : 0.0f);
    float q3 = (v.w > THRESH) ? 1.0f : ((v.w < -THRESH) ? -1.0f : 0.0f);
    __half2 h0 = __floats2half2_rn(q0, q1);
    __half2 h1 = __floats2half2_rn(q2, q3);
    uint32_t u0 = *(uint32_t*)&h0, u1 = *(uint32_t*)&h1;
    *(uint2*)(&g_B[i * 4]) = make_uint2(u0, u1);
}

// ===================== GEMM kernel =====================
// A fp16 [M][K] row-major, B fp16 [N][K] row-major (== B^T col-major: TN gemm).
// SMEM tile rows are 128B (64 halves); swizzle: 16B-chunk c -> c ^ (row & 7).
__global__ void __launch_bounds__(GTHREADS, 1)
gemm_kernel(float* __restrict__ out, const float* __restrict__ bias) {
    extern __shared__ __half smem[];
    const uint32_t sbase = smem_u32(smem);

    const int tid  = threadIdx.x;
    const int wid  = tid >> 5;
    const int lane = tid & 31;
    const int wm   = wid & 1;        // 0..1 : M
    const int wn   = wid >> 1;       // 0..3 : N

    const int m0 = blockIdx.y * BM;
    const int n0 = blockIdx.x * BN;

    const __half* gA = g_A + (size_t)m0 * K_TOTAL;
    const __half* gB = g_B + (size_t)n0 * K_TOTAL;

    const int ldrow = tid >> 3;      // 0..31
    const int ldcol = tid & 7;       // 16B chunk 0..7

    // ---- async stage loader ----
    auto issue_stage = [&](int kt, int s) {
        const uint32_t stA = sbase + s * STAGE_BYTES;
        const uint32_t stB = stA + BM * BK * 2;
        const int kofs = kt * BK + ldcol * 8;
        #pragma unroll
        for (int i = 0; i < 4; ++i) {
            const int row = ldrow + i * 32;
            const uint32_t sw = (uint32_t)((ldcol ^ (row & 7)) << 4);
            cp16(stA + row * 128 + sw, gA + (size_t)row * K_TOTAL + kofs);
            cp16(stB + row * 128 + sw, gB + (size_t)row * K_TOTAL + kofs);
        }
    };

    // prologue: stages 0,1
    issue_stage(0, 0); CP_COMMIT();
    issue_stage(1, 1); CP_COMMIT();

    float acc[4][4][4];
    #pragma unroll
    for (int i = 0; i < 4; ++i)
        #pragma unroll
        for (int j = 0; j < 4; ++j)
            #pragma unroll
            for (int e = 0; e < 4; ++e) acc[i][j][e] = 0.0f;

    const int NKT = K_TOTAL / BK;    // 64
    for (int kt = 0; kt < NKT; ++kt) {
        CP_WAIT1();
        __syncthreads();

        // prefetch stage kt+2 into slot consumed at iteration kt-1
        if (kt + 2 < NKT) issue_stage(kt + 2, (kt + 2) % STAGES);
        CP_COMMIT();   // unconditional: keeps group accounting uniform

        const int s = kt % STAGES;
        const uint32_t stA = sbase + s * STAGE_BYTES;
        const uint32_t stB = stA + BM * BK * 2;

        #pragma unroll
        for (int ks = 0; ks < 4; ++ks) {           // 4 x k16 per stage
            uint32_t afr[4][4];
            #pragma unroll
            for (int mf = 0; mf < 4; ++mf) {
                const int row = wm * 64 + mf * 16 + (lane & 15);
                const int chunk = 2 * ks + (lane >> 4);
                ldm_x4(afr[mf], stA + row * 128 + ((chunk ^ (row & 7)) << 4));
            }
            uint32_t bfr[2][4];
            #pragma unroll
            for (int nh = 0; nh < 2; ++nh) {
                const int row = wn * 32 + nh * 16 + (lane & 15);
                const int chunk = 2 * ks + (lane >> 4);
                ldm_x4(bfr[nh], stB + row * 128 + ((chunk ^ (row & 7)) << 4));
            }
            #pragma unroll
            for (int mf = 0; mf < 4; ++mf) {
                #pragma unroll
                for (int nf = 0; nf < 4; ++nf) {
                    const uint32_t b0 = bfr[nf >> 1][nf & 1];
                    const uint32_t b1 = bfr[nf >> 1][(nf & 1) + 2];
                    mma16816(acc[mf][nf], afr[mf], b0, b1);
                }
            }
        }
    }

    // ---- epilogue: regs -> gmem (+bias), float2 stores ----
    #pragma unroll
    for (int mf = 0; mf < 4; ++mf) {
        const int r = m0 + wm * 64 + mf * 16 + (lane >> 2);
        #pragma unroll
        for (int nf = 0; nf < 4; ++nf) {
            const int c = n0 + wn * 32 + nf * 8 + (lane & 3) * 2;
            const float2 bv = *(const float2*)(bias + c);
            float2 v0, v1;
            v0.x = acc[mf][nf][0] + bv.x;
            v0.y = acc[mf][nf][1] + bv.y;
            v1.x = acc[mf][nf][2] + bv.x;
            v1.y = acc[mf][nf][3] + bv.y;
            *(float2*)(out + (size_t)r * N_TOTAL + c)       = v0;
            *(float2*)(out + (size_t)(r + 8) * N_TOTAL + c) = v1;
        }
    }
}

// ===================== host launch =====================
extern "C" void kernel_launch(void* const* d_in, const int* in_sizes, int n_in,
                              void* d_out, int out_size) {
    const float* x = nullptr;
    const float* w = nullptr;
    const float* bias = nullptr;
    for (int i = 0; i < n_in; ++i) {
        if (in_sizes[i] == M_TOTAL * K_TOTAL)      x = (const float*)d_in[i];
        else if (in_sizes[i] == N_TOTAL * K_TOTAL) w = (const float*)d_in[i];
        else if (in_sizes[i] == N_TOTAL)           bias = (const float*)d_in[i];
    }
    float* out = (float*)d_out;

    // pack prepass
    {
        size_t tx = (size_t)M_TOTAL * K_TOTAL / 4;
        pack_x_kernel<<<(unsigned)((tx + 255) / 256), 256>>>((const float4*)x);
        size_t tw = (size_t)N_TOTAL * K_TOTAL / 4;
        pack_w_kernel<<<(unsigned)((tw + 255) / 256), 256>>>((const float4*)w);
    }

    // GEMM
    static bool attr_set = false;
    if (!attr_set) {
        cudaFuncSetAttribute(gemm_kernel,
                             cudaFuncAttributeMaxDynamicSharedMemorySize, SMEM_BYTES);
        attr_set = true;
    }
    dim3 grid(N_TOTAL / BN, M_TOTAL / BM);
    gemm_kernel<<<grid, GTHREADS, SMEM_BYTES>>>(out, bias);
}